// round 14
// baseline (speedup 1.0000x reference)
#include <cuda_runtime.h>
#include <cuda_fp16.h>
#include <math.h>
#include <cstdint>

#define CDIM 160
#define HW 12544
#define WIMG 112
#define NIMG 32
#define NTHREADS 256
#define TILE_PX 64
#define TILES_PER_CTA 7
#define NBLOCKS 896          // 896 * 7 * 64px = 32*12544 px

#define PA 168      // A smem pitch (fp16) -> conflict-free ldmatrix
#define PB 72       // B smem pitch (fp16) -> conflict-free ldmatrix.trans
#define PD 72       // staging pitch (halves)
#define BSIZE (CDIM * PB * 2)   // 23040 bytes, one B tile

// shared memory byte offsets
#define SM_BIAS  0
#define SM_SCALE 640
#define SM_SHIFT 1280
#define SM_A     2048                       // 160*168*2 = 53760
#define SM_B0    (SM_A + CDIM * PA * 2)     // 55808
#define SM_B1    (SM_B0 + BSIZE)            // 78848
#define SM_SSTG  (SM_B1 + BSIZE)            // 101888: 64ch x 72 halves = 9216
#define SM_TOTAL (SM_SSTG + 64 * PD * 2)    // 111104 (2 CTAs/SM)

// PRE-SHIFTED intermediate: yt[c][p] = (shifted y)[c][p], channel-major fp16.
__device__ __half g_yt[(size_t)NIMG * CDIM * HW + 16];

// ---------------------------------------------------------------------------
__device__ __forceinline__ uint32_t smem_u32(const void* p) {
    uint32_t a;
    asm("{ .reg .u64 t; cvta.to.shared.u64 t, %1; cvt.u32.u64 %0, t; }" : "=r"(a) : "l"(p));
    return a;
}
__device__ __forceinline__ void ldsm_x4(uint32_t* r, uint32_t addr) {
    asm volatile("ldmatrix.sync.aligned.m8n8.x4.shared.b16 {%0,%1,%2,%3}, [%4];"
        : "=r"(r[0]), "=r"(r[1]), "=r"(r[2]), "=r"(r[3]) : "r"(addr));
}
__device__ __forceinline__ void ldsm_x4t(uint32_t* r, uint32_t addr) {
    asm volatile("ldmatrix.sync.aligned.m8n8.x4.trans.shared.b16 {%0,%1,%2,%3}, [%4];"
        : "=r"(r[0]), "=r"(r[1]), "=r"(r[2]), "=r"(r[3]) : "r"(addr));
}
__device__ __forceinline__ void mma16816(float* d, const uint32_t* a, const uint32_t* b) {
    asm volatile("mma.sync.aligned.m16n8k16.row.col.f32.f16.f16.f32 "
        "{%0,%1,%2,%3}, {%4,%5,%6,%7}, {%8,%9}, {%0,%1,%2,%3};"
        : "+f"(d[0]), "+f"(d[1]), "+f"(d[2]), "+f"(d[3])
        : "r"(a[0]), "r"(a[1]), "r"(a[2]), "r"(a[3]), "r"(b[0]), "r"(b[1]));
}
__device__ __forceinline__ void cp_async16(uint32_t saddr, const void* gptr) {
    asm volatile("cp.async.cg.shared.global [%0], [%1], 16;" :: "r"(saddr), "l"(gptr));
}
#define CP_COMMIT() asm volatile("cp.async.commit_group;" ::: "memory")
#define CP_WAIT0()  asm volatile("cp.async.wait_group 0;" ::: "memory")

// fast exact-GELU: erf via Abramowitz-Stegun 7.1.26, |abs err| <= 1.5e-7
__device__ __forceinline__ float fast_gelu(float h) {
    const float x = h * 0.70710678118654752f;
    const float ax = fabsf(x);
    const float t = __fdividef(1.0f, fmaf(0.3275911f, ax, 1.0f));
    float p = fmaf(t, 1.061405429f, -1.453152027f);
    p = fmaf(t, p, 1.421413741f);
    p = fmaf(t, p, -0.284496736f);
    p = fmaf(t, p, 0.254829592f);
    p *= t;
    const float e = __expf(-ax * ax);
    const float erf_abs = fmaf(-p, e, 1.0f);
    const float erf_v = copysignf(erf_abs, x);
    return 0.5f * h * (1.0f + erf_v);
}

// ---------------------------------------------------------------------------
// Kernel 1: yt = scatter_shift( W_cat @ gelu(bn(x)) + b_cat )
// Row/center segments store directly from acc; only col-shift segs staged.
// ---------------------------------------------------------------------------
__global__ __launch_bounds__(NTHREADS, 2) void gemm1_mma(
    const float* __restrict__ x,
    const float* __restrict__ gamma, const float* __restrict__ beta,
    const float* __restrict__ rmean, const float* __restrict__ rvar,
    const float* __restrict__ Wt, const float* __restrict__ bt,
    const float* __restrict__ Wb, const float* __restrict__ bb,
    const float* __restrict__ Wr, const float* __restrict__ br,
    const float* __restrict__ Wl, const float* __restrict__ bl,
    const float* __restrict__ Wc, const float* __restrict__ bc) {
    extern __shared__ char smem[];
    const uint32_t sb = smem_u32(smem);
    const int tid = threadIdx.x;
    const int wid = tid >> 5, lane = tid & 31;
    float* bias_s  = (float*)(smem + SM_BIAS);
    float* scale_s = (float*)(smem + SM_SCALE);
    float* shift_s = (float*)(smem + SM_SHIFT);
    __half* Aw = (__half*)(smem + SM_A);
    __half* Sstg = (__half*)(smem + SM_SSTG);

    const float* Wseg[5] = {Wt, Wb, Wr, Wl, Wc};
    for (int idx = tid; idx < CDIM * CDIM; idx += NTHREADS) {
        int m = idx / CDIM;
        int k = idx - m * CDIM;
        Aw[m * PA + k] = __float2half_rn(Wseg[m >> 5][(m & 31) * CDIM + k]);
    }
    if (tid < CDIM) {
        const float* bp[5] = {bt, bb, br, bl, bc};
        bias_s[tid] = bp[tid >> 5][tid & 31];
        float s = gamma[tid] * rsqrtf(rvar[tid] + 1e-5f);
        scale_s[tid] = s;
        shift_s[tid] = beta[tid] - rmean[tid] * s;
    }
    __syncthreads();

    // prep mapping: chunk = tid&15 (4px each), channels chbase..chbase+9
    const int chunk = tid & 15;
    const int chbase = (tid >> 4) * 10;
    const int wm = wid >> 2, wn = wid & 3;
    const int tr = lane >> 2, tc = 2 * (lane & 3);

    // MMA lane addresses
    const uint32_t a_lane = (uint32_t)((wm * 80 + (lane & 15)) * (PA * 2) + (lane >> 4) * 16);
    const uint32_t b_lane = (uint32_t)((lane & 15) * (PB * 2) + (wn * 16 + (lane >> 4) * 8) * 2);
    const uint32_t Ab = sb + SM_A + a_lane;

    float4 v[5];

    auto issue_batch = [&](int tile, int j0) {
        const int b = (tile * TILE_PX) / HW;
        const int p0 = tile * TILE_PX - b * HW;
        const float* xb = x + (size_t)b * CDIM * HW + p0 + chunk * 4;
#pragma unroll
        for (int j = 0; j < 5; ++j)
            v[j] = __ldg((const float4*)(xb + (size_t)(chbase + j0 + j) * HW));
    };
    auto conv_one = [&](char* buf, int j, int j0) {
        const int k = chbase + j0 + j;
        const float sc = scale_s[k], sh = shift_s[k];
        float g0 = fast_gelu(fmaf(v[j].x, sc, sh));
        float g1 = fast_gelu(fmaf(v[j].y, sc, sh));
        float g2 = fast_gelu(fmaf(v[j].z, sc, sh));
        float g3 = fast_gelu(fmaf(v[j].w, sc, sh));
        __half2 o2[2];
        o2[0] = __floats2half2_rn(g0, g1);
        o2[1] = __floats2half2_rn(g2, g3);
        *(float2*)((__half*)buf + k * PB + chunk * 4) = *(float2*)o2;
    };

    // prologue: tile 0 into buf0
    issue_batch(blockIdx.x * TILES_PER_CTA, 0);
#pragma unroll
    for (int j = 0; j < 5; ++j) conv_one(smem + SM_B0, j, 0);
    issue_batch(blockIdx.x * TILES_PER_CTA, 5);
#pragma unroll
    for (int j = 0; j < 5; ++j) conv_one(smem + SM_B0, j, 5);
    __syncthreads();

    for (int t = 0; t < TILES_PER_CTA; ++t) {
        const int tile = blockIdx.x * TILES_PER_CTA + t;
        const int b = (tile * TILE_PX) / HW;
        const int p0 = tile * TILE_PX - b * HW;
        const uint32_t curbuf = (t & 1) ? SM_B1 : SM_B0;
        char* nxtbuf = smem + ((t & 1) ? SM_B0 : SM_B1);
        const bool more = (t + 1 < TILES_PER_CTA);

        if (more) issue_batch(tile + 1, 0);

        // MMA with interleaved conversion of batch 0
        float acc[5][2][4] = {};
        const uint32_t Bb = sb + curbuf + b_lane;
#pragma unroll
        for (int kk = 0; kk < 10; ++kk) {
            const int k0 = kk * 16;
            uint32_t a[5][4];
#pragma unroll
            for (int mi = 0; mi < 5; ++mi)
                ldsm_x4(a[mi], Ab + mi * 16 * (PA * 2) + k0 * 2);
            uint32_t bfr[4];
            ldsm_x4t(bfr, Bb + k0 * (PB * 2));
#pragma unroll
            for (int mi = 0; mi < 5; ++mi) {
                mma16816(acc[mi][0], a[mi], bfr);
                mma16816(acc[mi][1], a[mi], bfr + 2);
            }
            if (more && (kk & 1)) conv_one(nxtbuf, kk >> 1, 0);
        }

        if (more) issue_batch(tile + 1, 5);

        __half* yb = g_yt + (size_t)b * CDIM * HW;
        const int q0c = p0 + wn * 16 + tc;   // pair base col 0
        const int q1c = q0c + 8;             // pair base col 1

        // hybrid epilogue: direct stores for segs 0,1,4; stage segs 2,3
#pragma unroll
        for (int mi = 0; mi < 5; ++mi) {
#pragma unroll
            for (int row = 0; row < 2; ++row) {
                const int r = wm * 80 + mi * 16 + row * 8 + tr;
                const float bia = bias_s[r];
                const __half2 h0 = __floats2half2_rn(acc[mi][0][row * 2 + 0] + bia,
                                                     acc[mi][0][row * 2 + 1] + bia);
                const __half2 h1 = __floats2half2_rn(acc[mi][1][row * 2 + 0] + bia,
                                                     acc[mi][1][row * 2 + 1] + bia);
                const bool staged = (wm == 0) ? (mi == 4) : (mi < 3);
                if (staged) {                    // col-shift segs -> smem staging
                    __half* d = Sstg + (r - 64) * PD;
                    *(__half2*)(d + wn * 16 + tc) = h0;
                    *(__half2*)(d + wn * 16 + 8 + tc) = h1;
                } else {
                    __half* base = yb + (size_t)r * HW;
                    const int seg = r >> 5;      // 0,1 (wm0) or 4 (wm1)
                    if (seg == 0) {              // shift up: y[q] -> yt[q-112]
                        const int h0r = q0c / WIMG;
                        if (h0r > 0) {
                            *(__half2*)(base + q0c - WIMG) = h0;
                            *(__half2*)(base + q1c - WIMG) = h1;
                        } else {                 // zero the bottom border row
                            *(__half2*)(base + q0c + (WIMG - 1) * WIMG) = __half2half2(__ushort_as_half(0));
                            *(__half2*)(base + q1c + (WIMG - 1) * WIMG) = __half2half2(__ushort_as_half(0));
                        }
                    } else if (seg == 1) {       // shift down: -> yt[q+112]
                        const int h0r = q0c / WIMG;
                        if (h0r < WIMG - 1) {
                            *(__half2*)(base + q0c + WIMG) = h0;
                            *(__half2*)(base + q1c + WIMG) = h1;
                        } else {                 // zero the top border row
                            *(__half2*)(base + q0c - (WIMG - 1) * WIMG) = __half2half2(__ushort_as_half(0));
                            *(__half2*)(base + q1c - (WIMG - 1) * WIMG) = __half2half2(__ushort_as_half(0));
                        }
                    } else {                     // center
                        *(__half2*)(base + q0c) = h0;
                        *(__half2*)(base + q1c) = h1;
                    }
                }
            }
        }
        __syncthreads();                         // staging visible

        // writeout staged col-shift channels by 8-px spans: 512 spans, 2/thread
        {
#pragma unroll
            for (int i = 0; i < 2; ++i) {
                const int item = i * NTHREADS + tid;
                const int ch64 = item >> 3;          // 0..63
                const int ch = 64 + ch64;
                const int sp = item & 7;
                const int q = p0 + sp * 8;
                const int h = q / WIMG;
                const int w0 = q - h * WIMG;
                const uint4 v4 = *(const uint4*)(Sstg + ch64 * PD + sp * 8);
                __half* base = yb + (size_t)ch * HW;
                const uint32_t pa = (v4.x >> 16) | (v4.y << 16);
                const uint32_t pb = (v4.y >> 16) | (v4.z << 16);
                const uint32_t pc = (v4.z >> 16) | (v4.w << 16);
                if (ch < 96) {                       // seg2: yt[p]=y[p-1]
                    *(uint16_t*)(base + q + 1) = (uint16_t)(v4.x & 0xFFFFu);
                    *(uint32_t*)(base + q + 2) = pa;
                    *(uint32_t*)(base + q + 4) = pb;
                    *(uint32_t*)(base + q + 6) = pc;
                    if (w0 < 104) *(uint16_t*)(base + q + 8) = (uint16_t)(v4.w >> 16);
                    if (w0 == 0)  *(uint16_t*)(base + q) = 0;
                } else {                             // seg3: yt[p]=y[p+1]
                    if (w0 > 0) *(uint16_t*)(base + q - 1) = (uint16_t)(v4.x & 0xFFFFu);
                    *(uint32_t*)(base + q)     = pa;
                    *(uint32_t*)(base + q + 2) = pb;
                    *(uint32_t*)(base + q + 4) = pc;
                    *(uint16_t*)(base + q + 6) = (uint16_t)(v4.w >> 16);
                    if (w0 == 104) *(uint16_t*)(base + q + 7) = 0;
                }
            }
        }

        if (more) {
#pragma unroll
            for (int j = 0; j < 5; ++j) conv_one(nxtbuf, j, 5);
        }
        __syncthreads();                    // tile end
    }
}

// ---------------------------------------------------------------------------
// Kernel 2: out = W_fuse @ yt + b_fuse   (cp.async 16B prefetch for B)
// ---------------------------------------------------------------------------
__global__ __launch_bounds__(NTHREADS, 2) void gemm2_mma(
    const float* __restrict__ Wf, const float* __restrict__ bf,
    float* __restrict__ out) {
    extern __shared__ char smem[];
    const uint32_t sb = smem_u32(smem);
    const int tid = threadIdx.x;
    const int wid = tid >> 5, lane = tid & 31;
    float* bias_s = (float*)(smem + SM_BIAS);
    __half* Aw = (__half*)(smem + SM_A);

    for (int idx = tid; idx < CDIM * CDIM; idx += NTHREADS) {
        int m = idx / CDIM;
        int k = idx - m * CDIM;
        Aw[m * PA + k] = __float2half_rn(Wf[m * CDIM + k]);
    }
    if (tid < CDIM) bias_s[tid] = bf[tid];
    __syncthreads();

    const int slot = tid & 7;
    const int chbase = (tid >> 3) * 5;
    const int wm = wid >> 2, wn = wid & 3;
    const int tr = lane >> 2, tc = 2 * (lane & 3);

    const uint32_t a_lane = (uint32_t)((wm * 80 + (lane & 15)) * (PA * 2) + (lane >> 4) * 16);
    const uint32_t b_lane = (uint32_t)((lane & 15) * (PB * 2) + (wn * 16 + (lane >> 4) * 8) * 2);
    const uint32_t Ab = sb + SM_A + a_lane;

    auto issue_cp = [&](int tile, uint32_t bufoff) {
        const int b = (tile * TILE_PX) / HW;
        const int p0 = tile * TILE_PX - b * HW;
        const __half* yb = g_yt + (size_t)b * CDIM * HW + p0 + slot * 8;
#pragma unroll
        for (int j = 0; j < 5; ++j)
            cp_async16(sb + bufoff + (uint32_t)(((chbase + j) * PB + slot * 8) * 2),
                       yb + (size_t)(chbase + j) * HW);
        CP_COMMIT();
    };

    issue_cp(blockIdx.x * TILES_PER_CTA, SM_B0);
    CP_WAIT0();
    __syncthreads();

    for (int t = 0; t < TILES_PER_CTA; ++t) {
        const int tile = blockIdx.x * TILES_PER_CTA + t;
        const int b = (tile * TILE_PX) / HW;
        const int p0 = tile * TILE_PX - b * HW;
        const uint32_t curbuf = (t & 1) ? SM_B1 : SM_B0;
        const uint32_t nxtoff = (t & 1) ? SM_B0 : SM_B1;

        if (t + 1 < TILES_PER_CTA) issue_cp(tile + 1, nxtoff);  // async under MMA

        float acc[5][2][4] = {};
        const uint32_t Bb = sb + curbuf + b_lane;
#pragma unroll
        for (int kk = 0; kk < 10; ++kk) {
            const int k0 = kk * 16;
            uint32_t a[5][4];
#pragma unroll
            for (int mi = 0; mi < 5; ++mi)
                ldsm_x4(a[mi], Ab + mi * 16 * (PA * 2) + k0 * 2);
            uint32_t bfr[4];
            ldsm_x4t(bfr, Bb + k0 * (PB * 2));
#pragma unroll
            for (int mi = 0; mi < 5; ++mi) {
                mma16816(acc[mi][0], a[mi], bfr);
                mma16816(acc[mi][1], a[mi], bfr + 2);
            }
        }

        CP_WAIT0();                                  // next tile landed

        float* ob = out + (size_t)b * CDIM * HW + p0;
#pragma unroll
        for (int mi = 0; mi < 5; ++mi) {
            const int r0 = wm * 80 + mi * 16 + tr;
            const float bia0 = bias_s[r0];
            const float bia1 = bias_s[r0 + 8];
#pragma unroll
            for (int ni = 0; ni < 2; ++ni) {
                const int c = wn * 16 + ni * 8 + tc;
                *(float2*)(ob + (size_t)r0 * HW + c) =
                    make_float2(acc[mi][ni][0] + bia0, acc[mi][ni][1] + bia0);
                *(float2*)(ob + (size_t)(r0 + 8) * HW + c) =
                    make_float2(acc[mi][ni][2] + bia1, acc[mi][ni][3] + bia1);
            }
        }
        __syncthreads();
    }
}

// ---------------------------------------------------------------------------
extern "C" void kernel_launch(void* const* d_in, const int* in_sizes, int n_in,
                              void* d_out, int out_size) {
    const float* x     = (const float*)d_in[0];
    const float* gamma = (const float*)d_in[1];
    const float* beta  = (const float*)d_in[2];
    const float* rmean = (const float*)d_in[3];
    const float* rvar  = (const float*)d_in[4];
    const float* Wt = (const float*)d_in[5];  const float* bt = (const float*)d_in[6];
    const float* Wb = (const float*)d_in[7];  const float* bb = (const float*)d_in[8];
    const float* Wr = (const float*)d_in[9];  const float* br = (const float*)d_in[10];
    const float* Wl = (const float*)d_in[11]; const float* bl = (const float*)d_in[12];
    const float* Wc = (const float*)d_in[13]; const float* bc = (const float*)d_in[14];
    const float* Wf = (const float*)d_in[15]; const float* bf = (const float*)d_in[16];

    cudaFuncSetAttribute(gemm1_mma, cudaFuncAttributeMaxDynamicSharedMemorySize, SM_TOTAL);
    cudaFuncSetAttribute(gemm2_mma, cudaFuncAttributeMaxDynamicSharedMemorySize, SM_TOTAL);

    gemm1_mma<<<NBLOCKS, NTHREADS, SM_TOTAL>>>(x, gamma, beta, rmean, rvar,
                                               Wt, bt, Wb, bb, Wr, br, Wl, bl, Wc, bc);
    gemm2_mma<<<NBLOCKS, NTHREADS, SM_TOTAL>>>(Wf, bf, (float*)d_out);
}